// round 14
// baseline (speedup 1.0000x reference)
#include <cuda_runtime.h>
#include <math.h>
#include <stdint.h>

// Problem shapes
#define B_   2
#define H_   48
#define W_   48
#define C_   256
#define NH_  8
#define HD_  32
#define L_   2304          // H_*W_
#define ML_  4608          // B_*L_

#define KSCALE 0.17677669529663687f   // 32^-0.5

// ---------------------------------------------------------------------------
// Scratch (static __device__ — no allocations allowed)
// d-permuted layouts (chosen for LDS.128 fragment loads in attention):
//   g_q, g_k : pos(d) = (d%4)*8 + d/4   (K-style: thread needs d ≡ tg mod 4)
//   g_v      : pos(d) = (d%8)*4 + d/8   (V-style: thread needs d ≡ gp mod 8)
// ---------------------------------------------------------------------------
__device__ float g_q[B_ * NH_ * L_ * HD_];
__device__ float g_k[B_ * NH_ * L_ * HD_];
__device__ float g_v[B_ * NH_ * L_ * HD_];
__device__ float g_lepe[ML_ * C_];          // [row, C] logical d
__device__ float g_attn[ML_ * C_];          // [row, C] logical d (attn + lepe)

// ---------------------------------------------------------------------------
// Helpers
// ---------------------------------------------------------------------------
__device__ __forceinline__ float tf32r(float x) {
    unsigned u;
    asm("cvt.rna.tf32.f32 %0, %1;" : "=r"(u) : "f"(x));
    return __uint_as_float(u);
}
#define U_(x) __float_as_uint(x)

__device__ __forceinline__ void mma_tf32(float* d, const unsigned* a,
                                         unsigned b0, unsigned b1) {
    asm volatile(
        "mma.sync.aligned.m16n8k8.row.col.f32.tf32.tf32.f32 "
        "{%0,%1,%2,%3}, {%4,%5,%6,%7}, {%8,%9}, {%0,%1,%2,%3};\n"
        : "+f"(d[0]), "+f"(d[1]), "+f"(d[2]), "+f"(d[3])
        : "r"(a[0]), "r"(a[1]), "r"(a[2]), "r"(a[3]), "r"(b0), "r"(b1));
}

__device__ __forceinline__ void cp16(uint32_t dst, const float* src) {
    asm volatile("cp.async.cg.shared.global [%0], [%1], 16;\n"
                 :: "r"(dst), "l"(src));
}
__device__ __forceinline__ void cp_commit() {
    asm volatile("cp.async.commit_group;\n");
}
__device__ __forceinline__ void cp_wait_all() {
    asm volatile("cp.async.wait_group 0;\n" ::: "memory");
}

__device__ __forceinline__ int posK(int d) { return (d & 3) * 8 + (d >> 2); }
__device__ __forceinline__ int posV(int d) { return (d & 7) * 4 + (d >> 3); }

// ===========================================================================
// QKV projection, 3xTF32 split GEMM, cp.async double-buffered k-loop, fused
// bias + k-scale + RoPE + permuted layout scatter. (unchanged from R13)
// Tile 64M x 64N, 256 thr. Grid (12, 72) = 864 blocks -> 2 CTAs/SM.
// ===========================================================================
#define QKV_SMEM (2 * (64 * 36 + 32 * 72) * 4)     // 36864 B

__global__ __launch_bounds__(256, 2) void qkv_gemm(
    const float* __restrict__ x,
    const float* __restrict__ wq, const float* __restrict__ wk,
    const float* __restrict__ wv,
    const float* __restrict__ bq, const float* __restrict__ bk,
    const float* __restrict__ bv,
    const float* __restrict__ sinp, const float* __restrict__ cosp)
{
    extern __shared__ float smg[];
    float* As[2] = { smg,        smg + 4608 };         // [64][36]
    float* Bs[2] = { smg + 2304, smg + 4608 + 2304 };  // [32][72]

    int tid = threadIdx.x;
    int wid = tid >> 5, lane = tid & 31;
    int gp = lane >> 2, tg = lane & 3;
    int wm = wid & 1, wn = wid >> 1;
    int m0 = blockIdx.y * 64;
    int n0 = blockIdx.x * 64;
    int sel = n0 >> 8;               // 0=q 1=k 2=v
    const float* Wm = (sel == 0) ? wq : ((sel == 1) ? wk : wv);
    int nl = n0 & 255;

    int ea_row[2], ea_c4[2], eb_row[2], eb_c4[2];
    uint32_t adst[2][2], bdst[2][2];
#pragma unroll
    for (int i = 0; i < 2; i++) {
        int e = tid + i * 256;
        ea_row[i] = e >> 3;  ea_c4[i] = (e & 7) * 4;
        eb_row[i] = e >> 4;  eb_c4[i] = (e & 15) * 4;
#pragma unroll
        for (int s = 0; s < 2; s++) {
            adst[s][i] = (uint32_t)__cvta_generic_to_shared(
                As[s] + ea_row[i] * 36 + ea_c4[i]);
            bdst[s][i] = (uint32_t)__cvta_generic_to_shared(
                Bs[s] + eb_row[i] * 72 + eb_c4[i]);
        }
    }

#pragma unroll
    for (int i = 0; i < 2; i++) {
        cp16(adst[0][i], x + (size_t)(m0 + ea_row[i]) * 256 + ea_c4[i]);
        cp16(bdst[0][i], Wm + (size_t)eb_row[i] * 256 + nl + eb_c4[i]);
    }
    cp_commit();

    float c[2][2][4];
#pragma unroll
    for (int mf = 0; mf < 2; mf++)
#pragma unroll
        for (int nf = 0; nf < 2; nf++)
#pragma unroll
            for (int q = 0; q < 4; q++) c[mf][nf][q] = 0.f;

    for (int it = 0; it < 8; it++) {
        int cur = it & 1;
        cp_wait_all();
        __syncthreads();
        if (it < 7) {
            int k1 = (it + 1) * 32;
#pragma unroll
            for (int i = 0; i < 2; i++) {
                cp16(adst[cur ^ 1][i],
                     x + (size_t)(m0 + ea_row[i]) * 256 + k1 + ea_c4[i]);
                cp16(bdst[cur ^ 1][i],
                     Wm + (size_t)(k1 + eb_row[i]) * 256 + nl + eb_c4[i]);
            }
            cp_commit();
        }
        const float* Ac = As[cur];
        const float* Bc = Bs[cur];
#pragma unroll
        for (int kc = 0; kc < 4; kc++) {
            int kk = kc * 8 + tg;
            unsigned ah[2][4], al[2][4], bh[2][2], bl[2][2];
#pragma unroll
            for (int mf = 0; mf < 2; mf++) {
                int r = wm * 32 + mf * 16 + gp;
                float a0 = Ac[r * 36 + kk],       a1 = Ac[(r + 8) * 36 + kk];
                float a2 = Ac[r * 36 + kk + 4],   a3 = Ac[(r + 8) * 36 + kk + 4];
                float h0 = tf32r(a0), h1 = tf32r(a1), h2 = tf32r(a2), h3 = tf32r(a3);
                ah[mf][0] = U_(h0); ah[mf][1] = U_(h1);
                ah[mf][2] = U_(h2); ah[mf][3] = U_(h3);
                al[mf][0] = U_(a0 - h0); al[mf][1] = U_(a1 - h1);
                al[mf][2] = U_(a2 - h2); al[mf][3] = U_(a3 - h3);
            }
#pragma unroll
            for (int nf = 0; nf < 2; nf++) {
                int cc = wn * 16 + nf * 8 + gp;
                float b0 = Bc[kk * 72 + cc], b1 = Bc[(kk + 4) * 72 + cc];
                float h0 = tf32r(b0), h1 = tf32r(b1);
                bh[nf][0] = U_(h0); bh[nf][1] = U_(h1);
                bl[nf][0] = U_(b0 - h0); bl[nf][1] = U_(b1 - h1);
            }
#pragma unroll
            for (int mf = 0; mf < 2; mf++)
#pragma unroll
                for (int nf = 0; nf < 2; nf++) {
                    mma_tf32(c[mf][nf], ah[mf], bh[nf][0], bh[nf][1]);
                    mma_tf32(c[mf][nf], al[mf], bh[nf][0], bh[nf][1]);
                    mma_tf32(c[mf][nf], ah[mf], bl[nf][0], bl[nf][1]);
                }
        }
        __syncthreads();
    }

    // ---- epilogue: bias (+scale) (+rope) + permuted scatter ----
#pragma unroll
    for (int mf = 0; mf < 2; mf++) {
#pragma unroll
        for (int nf = 0; nf < 2; nf++) {
            int colg = n0 + wn * 16 + nf * 8 + 2 * tg;
            int cl = colg & 255;
            int d = cl & 31, head = cl >> 5;
#pragma unroll
            for (int half = 0; half < 2; half++) {
                int row = m0 + wm * 32 + mf * 16 + gp + half * 8;
                float v0 = c[mf][nf][half * 2 + 0];
                float v1 = c[mf][nf][half * 2 + 1];
                int bb = row / L_, l = row - bb * L_;
                size_t base = ((size_t)(bb * NH_ + head) * L_ + l) * HD_;
                if (sel == 0) {
                    v0 += bq[cl]; v1 += bq[cl + 1];
                    float s0 = sinp[l * HD_ + d], s1 = sinp[l * HD_ + d + 1];
                    float c0 = cosp[l * HD_ + d], c1 = cosp[l * HD_ + d + 1];
                    g_q[base + posK(d)]     = v0 * c0 - v1 * s0;
                    g_q[base + posK(d + 1)] = v1 * c1 + v0 * s1;
                } else if (sel == 1) {
                    v0 = (v0 + bk[cl]) * KSCALE;
                    v1 = (v1 + bk[cl + 1]) * KSCALE;
                    float s0 = sinp[l * HD_ + d], s1 = sinp[l * HD_ + d + 1];
                    float c0 = cosp[l * HD_ + d], c1 = cosp[l * HD_ + d + 1];
                    g_k[base + posK(d)]     = v0 * c0 - v1 * s0;
                    g_k[base + posK(d + 1)] = v1 * c1 + v0 * s1;
                } else {
                    g_v[base + posV(d)]     = v0 + bv[cl];
                    g_v[base + posV(d + 1)] = v1 + bv[cl + 1];
                }
            }
        }
    }
}

// ===========================================================================
// Output projection, 3xTF32 split GEMM, store-side split (R10 form, measured
// faster than load-side split):  out[4608 x 256] = g_attn @ wo + bo.
// Tile 64M x 64N, grid (4, 72) = 288 blocks -> 2 CTAs/SM.
// ===========================================================================
#define OGEMM_SMEM ((2 * 64 * 36 + 2 * 32 * 72) * 4)     // 36864 B

__global__ __launch_bounds__(256, 2) void out_gemm(
    const float* __restrict__ wo, const float* __restrict__ bo,
    float* __restrict__ out)
{
    extern __shared__ float smg[];
    float* Ah = smg;                 // [64][36]
    float* Al = Ah + 64 * 36;
    float* Bh = Al + 64 * 36;        // [32][72]
    float* Bl = Bh + 32 * 72;

    int tid = threadIdx.x;
    int wid = tid >> 5, lane = tid & 31;
    int gp = lane >> 2, tg = lane & 3;
    int wm = wid & 1, wn = wid >> 1;
    int m0 = blockIdx.y * 64;
    int n0 = blockIdx.x * 64;

    float c[2][2][4];
#pragma unroll
    for (int mf = 0; mf < 2; mf++)
#pragma unroll
        for (int nf = 0; nf < 2; nf++)
#pragma unroll
            for (int q = 0; q < 4; q++) c[mf][nf][q] = 0.f;

    for (int k0 = 0; k0 < 256; k0 += 32) {
#pragma unroll
        for (int i = 0; i < 2; i++) {
            int e = tid + i * 256;
            int row = e >> 3, c4 = (e & 7) * 4;
            size_t off = (size_t)(m0 + row) * 256 + k0 + c4;
            float4 a4 = *(const float4*)(g_attn + off);
            float h0 = tf32r(a4.x), h1 = tf32r(a4.y),
                  h2 = tf32r(a4.z), h3 = tf32r(a4.w);
            float* ah = Ah + row * 36 + c4;
            float* al = Al + row * 36 + c4;
            ah[0] = h0; ah[1] = h1; ah[2] = h2; ah[3] = h3;
            al[0] = a4.x - h0; al[1] = a4.y - h1;
            al[2] = a4.z - h2; al[3] = a4.w - h3;
        }
#pragma unroll
        for (int i = 0; i < 2; i++) {
            int e = tid + i * 256;
            int row = e >> 4, c4 = (e & 15) * 4;
            float4 b4 = *(const float4*)(wo + (size_t)(k0 + row) * 256 + n0 + c4);
            float h0 = tf32r(b4.x), h1 = tf32r(b4.y),
                  h2 = tf32r(b4.z), h3 = tf32r(b4.w);
            float* bh = Bh + row * 72 + c4;
            float* bl = Bl + row * 72 + c4;
            bh[0] = h0; bh[1] = h1; bh[2] = h2; bh[3] = h3;
            bl[0] = b4.x - h0; bl[1] = b4.y - h1;
            bl[2] = b4.z - h2; bl[3] = b4.w - h3;
        }
        __syncthreads();
#pragma unroll
        for (int kc = 0; kc < 4; kc++) {
            int kk = kc * 8 + tg;
            unsigned ah[2][4], al[2][4], bh[2][2], bl[2][2];
#pragma unroll
            for (int mf = 0; mf < 2; mf++) {
                int r = wm * 32 + mf * 16 + gp;
                ah[mf][0] = U_(Ah[r * 36 + kk]);
                ah[mf][1] = U_(Ah[(r + 8) * 36 + kk]);
                ah[mf][2] = U_(Ah[r * 36 + kk + 4]);
                ah[mf][3] = U_(Ah[(r + 8) * 36 + kk + 4]);
                al[mf][0] = U_(Al[r * 36 + kk]);
                al[mf][1] = U_(Al[(r + 8) * 36 + kk]);
                al[mf][2] = U_(Al[r * 36 + kk + 4]);
                al[mf][3] = U_(Al[(r + 8) * 36 + kk + 4]);
            }
#pragma unroll
            for (int nf = 0; nf < 2; nf++) {
                int cc = wn * 16 + nf * 8 + gp;
                bh[nf][0] = U_(Bh[kk * 72 + cc]);
                bh[nf][1] = U_(Bh[(kk + 4) * 72 + cc]);
                bl[nf][0] = U_(Bl[kk * 72 + cc]);
                bl[nf][1] = U_(Bl[(kk + 4) * 72 + cc]);
            }
#pragma unroll
            for (int mf = 0; mf < 2; mf++)
#pragma unroll
                for (int nf = 0; nf < 2; nf++) {
                    mma_tf32(c[mf][nf], ah[mf], bh[nf][0], bh[nf][1]);
                    mma_tf32(c[mf][nf], al[mf], bh[nf][0], bh[nf][1]);
                    mma_tf32(c[mf][nf], ah[mf], bl[nf][0], bl[nf][1]);
                }
        }
        __syncthreads();
    }

#pragma unroll
    for (int mf = 0; mf < 2; mf++)
#pragma unroll
        for (int nf = 0; nf < 2; nf++) {
            int colg = n0 + wn * 16 + nf * 8 + 2 * tg;
            float b0 = bo[colg], b1 = bo[colg + 1];
#pragma unroll
            for (int half = 0; half < 2; half++) {
                int row = m0 + wm * 32 + mf * 16 + gp + half * 8;
                *(float2*)(out + (size_t)row * 256 + colg) =
                    make_float2(c[mf][nf][half * 2 + 0] + b0,
                                c[mf][nf][half * 2 + 1] + b1);
            }
        }
}

// ---------------------------------------------------------------------------
// Depthwise 5x5 conv (lepe) on v (V-permuted layout), padding 2 -> [row, C]
// ---------------------------------------------------------------------------
__global__ __launch_bounds__(256) void dwconv_kernel(
    const float* __restrict__ wdw, const float* __restrict__ bdw)
{
    __shared__ float tile[144][32];   // 12x12 halo x 32 stored-positions
    int b = blockIdx.z, n = blockIdx.y;
    int t = blockIdx.x;
    int ty0 = (t / 6) * 8, tx0 = (t % 6) * 8;
    const float* vb = g_v + (size_t)(b * NH_ + n) * L_ * HD_;

    for (int e = threadIdx.x; e < 144 * 32; e += 256) {
        int ch = e & 31, sp = e >> 5;
        int hy = ty0 + sp / 12 - 2, wx = tx0 + sp % 12 - 2;
        float val = 0.f;
        if (hy >= 0 && hy < H_ && wx >= 0 && wx < W_)
            val = vb[(size_t)(hy * W_ + wx) * HD_ + ch];
        tile[sp][ch] = val;
    }
    __syncthreads();

    for (int o = threadIdx.x; o < 64 * 32; o += 256) {
        int ch = o & 31, sp = o >> 5;           // ch = stored position
        int dlog = (ch & 3) * 8 + (ch >> 2);    // invert posV
        int y = sp >> 3, x = sp & 7;
        float acc = bdw[n * 32 + dlog];
#pragma unroll
        for (int ky = 0; ky < 5; ky++)
#pragma unroll
            for (int kx = 0; kx < 5; kx++)
                acc = fmaf(tile[(y + ky) * 12 + x + kx][ch],
                           wdw[(ky * 5 + kx) * 256 + n * 32 + dlog], acc);
        g_lepe[((size_t)(b * L_) + (ty0 + y) * W_ + tx0 + x) * 256 + n * 32 + dlog] = acc;
    }
}

// ---------------------------------------------------------------------------
// Flash attention v8 — 32 q-rows per warp: halves K/V smem fragment traffic
// (the computed crossbar floor was the binding pipe).
//  * 256 threads (8 warps x 32 rows = 256 q-rows/CTA), grid (B,9,NH) = 144
//    = one full wave, 1 CTA/SM (register file spent on ILP, not TLP — R10
//    showed extra CTAs/SM buy nothing here)
//  * each 2x LDS.128 K/V fragment now feeds 8 MMAs (was 4)
//  * 64-key tiles, cp.async double-buffered K/V, mask folded into accum init
//  * no max-shift softmax (bounded scores), per-thread deferred denominators
//  * shfl-free P path via permuted V rows (register relabel {s0,s2,s1,s3})
// Smem: Q[256][36] + 2xK[64][36] + 2xV[64][40] = 75776 B.
// ---------------------------------------------------------------------------
#define ATTN_SMEM (size_t)(75776)

__global__ __launch_bounds__(256) void attn_kernel(const float* __restrict__ mask)
{
    extern __shared__ float sm[];
    float* Qs = sm;                                  // 256 x 36 = 9216 f
    float* Kb[2] = { sm + 9216,  sm + 11520 };       // 64 x 36 each
    float* Vb[2] = { sm + 13824, sm + 16384 };       // 64 x 40 each

    int b = blockIdx.x, qt = blockIdx.y, n = blockIdx.z;
    int bn = b * NH_ + n;
    const float* qb = g_q + (size_t)bn * L_ * HD_;
    const float* kb = g_k + (size_t)bn * L_ * HD_;
    const float* vb = g_v + (size_t)bn * L_ * HD_;
    int q0 = qt * 256;

    int tid = threadIdx.x;
    int wr = tid >> 5;        // 0..7, warp owns rows [wr*32, wr*32+32)
    int lane = tid & 31;
    int gp = lane >> 2;
    int tg = lane & 3;
    int r0 = wr * 32 + gp;    // block0: rows r0, r0+8 ; block1: r0+16, r0+24

    // cp.async mapping: 64 rows x 8 chunks(16B) = 512 -> 2 chunks per thread
    uint32_t kdst[2][2], vdst[2][2];
    const float *ksrc[2], *vsrc[2];
#pragma unroll
    for (int i = 0; i < 2; i++) {
        int e = tid + i * 256;
        int erow = e >> 3;
        int ecol = (e & 7) * 4;
        // V row permutation: key loc -> slot (loc>>1)+(loc&1)*4 within 8-group
        int vrow = (erow & ~7) + ((erow & 7) >> 1) + ((erow & 1) << 2);
        kdst[0][i] = (uint32_t)__cvta_generic_to_shared(Kb[0] + erow * 36 + ecol);
        kdst[1][i] = (uint32_t)__cvta_generic_to_shared(Kb[1] + erow * 36 + ecol);
        vdst[0][i] = (uint32_t)__cvta_generic_to_shared(Vb[0] + vrow * 40 + ecol);
        vdst[1][i] = (uint32_t)__cvta_generic_to_shared(Vb[1] + vrow * 40 + ecol);
        ksrc[i] = kb + (size_t)erow * HD_ + ecol;
        vsrc[i] = vb + (size_t)erow * HD_ + ecol;
    }

    const float* mbase = mask + (size_t)n * L_ * L_ + (size_t)(q0 + r0) * L_;

    // ---- prologue ----
#pragma unroll
    for (int i = 0; i < 2; i++) {
        cp16(kdst[0][i], ksrc[i]);
        cp16(vdst[0][i], vsrc[i]);
    }
    cp_commit();

    for (int e = tid; e < 256 * 8; e += 256) {
        int row = e >> 3, cq = (e & 7) * 4;
        *(float4*)(Qs + row * 36 + cq) =
            *(const float4*)(qb + (size_t)(q0 + row) * HD_ + cq);
    }
    __syncthreads();

    // ---- Q A-fragments for both 16-row blocks (4x LDS.128 per block pair) ----
    unsigned qa[4][4], qbf[4][4];
#pragma unroll
    for (int blk = 0; blk < 2; blk++) {
        unsigned (*qf)[4] = blk ? qbf : qa;
        int rr = r0 + blk * 16;
        float4 qL0 = *(const float4*)(Qs + rr * 36 + tg * 8);
        float4 qL1 = *(const float4*)(Qs + rr * 36 + tg * 8 + 4);
        float4 qH0 = *(const float4*)(Qs + (rr + 8) * 36 + tg * 8);
        float4 qH1 = *(const float4*)(Qs + (rr + 8) * 36 + tg * 8 + 4);
        qf[0][0] = U_(qL0.x); qf[0][1] = U_(qH0.x); qf[0][2] = U_(qL0.y); qf[0][3] = U_(qH0.y);
        qf[1][0] = U_(qL0.z); qf[1][1] = U_(qH0.z); qf[1][2] = U_(qL0.w); qf[1][3] = U_(qH0.w);
        qf[2][0] = U_(qL1.x); qf[2][1] = U_(qH1.x); qf[2][2] = U_(qL1.y); qf[2][3] = U_(qH1.y);
        qf[3][0] = U_(qL1.z); qf[3][1] = U_(qH1.z); qf[3][2] = U_(qL1.w); qf[3][3] = U_(qH1.w);
    }

    float ps0_lo = 0.f, ps0_hi = 0.f, ps1_lo = 0.f, ps1_hi = 0.f;
    float O0[4][4], O1[4][4];
#pragma unroll
    for (int j = 0; j < 4; j++) {
        O0[j][0] = O0[j][1] = O0[j][2] = O0[j][3] = 0.f;
        O1[j][0] = O1[j][1] = O1[j][2] = O1[j][3] = 0.f;
    }

    for (int kt = 0; kt < 36; kt++) {
        int k0 = kt * 64;
        int cur = kt & 1;

        // ---- mask loads first (latency overlaps cp.async wait) ----
        float s0[8][4], s1[8][4];
        {
            const float* mp = mbase + k0;
#pragma unroll
            for (int j = 0; j < 8; j++) {
                int col = j * 8 + 2 * tg;
                float2 mA = *(const float2*)(mp + col);
                float2 mB = *(const float2*)(mp + (size_t)8 * L_ + col);
                float2 mC = *(const float2*)(mp + (size_t)16 * L_ + col);
                float2 mD = *(const float2*)(mp + (size_t)24 * L_ + col);
                s0[j][0] = mA.x; s0[j][1] = mA.y; s0[j][2] = mB.x; s0[j][3] = mB.y;
                s1[j][0] = mC.x; s1[j][1] = mC.y; s1[j][2] = mD.x; s1[j][3] = mD.y;
            }
        }

        cp_wait_all();
        __syncthreads();

        if (kt + 1 < 36) {
#pragma unroll
            for (int i = 0; i < 2; i++) {
                cp16(kdst[cur ^ 1][i], ksrc[i] + (size_t)(k0 + 64) * HD_);
                cp16(vdst[cur ^ 1][i], vsrc[i] + (size_t)(k0 + 64) * HD_);
            }
            cp_commit();
        }

        const float* Ks = Kb[cur];
        const float* Vs = Vb[cur];

        // ---- S = mask + Q @ K^T : 2 LDS.128 feed 8 MMAs ----
#pragma unroll
        for (int j = 0; j < 8; j++) {
            const float* kr = Ks + (8 * j + gp) * 36 + tg * 8;
            float4 kf0 = *(const float4*)(kr);
            float4 kf1 = *(const float4*)(kr + 4);
            mma_tf32(s0[j], qa[0], U_(kf0.x), U_(kf0.y));
            mma_tf32(s0[j], qa[1], U_(kf0.z), U_(kf0.w));
            mma_tf32(s0[j], qa[2], U_(kf1.x), U_(kf1.y));
            mma_tf32(s0[j], qa[3], U_(kf1.z), U_(kf1.w));
            mma_tf32(s1[j], qbf[0], U_(kf0.x), U_(kf0.y));
            mma_tf32(s1[j], qbf[1], U_(kf0.z), U_(kf0.w));
            mma_tf32(s1[j], qbf[2], U_(kf1.x), U_(kf1.y));
            mma_tf32(s1[j], qbf[3], U_(kf1.z), U_(kf1.w));
        }

        // ---- P = exp(S) (no max-shift; bounded scores), accumulate denoms ----
#pragma unroll
        for (int j = 0; j < 8; j++) {
            s0[j][0] = __expf(s0[j][0]); s0[j][1] = __expf(s0[j][1]);
            s0[j][2] = __expf(s0[j][2]); s0[j][3] = __expf(s0[j][3]);
            ps0_lo += s0[j][0] + s0[j][1];
            ps0_hi += s0[j][2] + s0[j][3];
            s1[j][0] = __expf(s1[j][0]); s1[j][1] = __expf(s1[j][1]);
            s1[j][2] = __expf(s1[j][2]); s1[j][3] = __expf(s1[j][3]);
            ps1_lo += s1[j][0] + s1[j][1];
            ps1_hi += s1[j][2] + s1[j][3];
        }

        // ---- O += P @ V : 2 LDS.128 feed 8 MMAs ----
#pragma unroll
        for (int kc2 = 0; kc2 < 8; kc2++) {
            unsigned pa0[4], pa1[4];
            pa0[0] = U_(s0[kc2][0]); pa0[1] = U_(s0[kc2][2]);
            pa0[2] = U_(s0[kc2][1]); pa0[3] = U_(s0[kc2][3]);
            pa1[0] = U_(s1[kc2][0]); pa1[1] = U_(s1[kc2][2]);
            pa1[2] = U_(s1[kc2][1]); pa1[3] = U_(s1[kc2][3]);
            float4 vA = *(const float4*)(Vs + (kc2 * 8 + tg) * 40 + gp * 4);
            float4 vB = *(const float4*)(Vs + (kc2 * 8 + tg + 4) * 40 + gp * 4);
            mma_tf32(O0[0], pa0, U_(vA.x), U_(vB.x));
            mma_tf32(O0[1], pa0, U_(vA.y), U_(vB.y));
            mma_tf32(O0[2], pa0, U_(vA.z), U_(vB.z));
            mma_tf32(O0[3], pa0, U_(vA.w), U_(vB.w));
            mma_tf32(O1[0], pa1, U_(vA.x), U_(vB.x));
            mma_tf32(O1[1], pa1, U_(vA.y), U_(vB.y));
            mma_tf32(O1[2], pa1, U_(vA.z), U_(vB.z));
            mma_tf32(O1[3], pa1, U_(vA.w), U_(vB.w));
        }
    }

    // ---- epilogue: reduce denoms, O / l + lepe, write logical d ----
    ps0_lo += __shfl_xor_sync(0xffffffffu, ps0_lo, 1);
    ps0_lo += __shfl_xor_sync(0xffffffffu, ps0_lo, 2);
    ps0_hi += __shfl_xor_sync(0xffffffffu, ps0_hi, 1);
    ps0_hi += __shfl_xor_sync(0xffffffffu, ps0_hi, 2);
    ps1_lo += __shfl_xor_sync(0xffffffffu, ps1_lo, 1);
    ps1_lo += __shfl_xor_sync(0xffffffffu, ps1_lo, 2);
    ps1_hi += __shfl_xor_sync(0xffffffffu, ps1_hi, 1);
    ps1_hi += __shfl_xor_sync(0xffffffffu, ps1_hi, 2);
    float i0l = 1.f / ps0_lo, i0h = 1.f / ps0_hi;
    float i1l = 1.f / ps1_lo, i1h = 1.f / ps1_hi;

#pragma unroll
    for (int blk = 0; blk < 2; blk++) {
        float (*O)[4] = blk ? O1 : O0;
        float il = blk ? i1l : i0l, ih = blk ? i1h : i0h;
        size_t obase = (size_t)(b * L_ + q0 + r0 + blk * 16) * 256 + n * 32;
        float* ob_lo = g_attn + obase;
        float* ob_hi = ob_lo + (size_t)8 * 256;
        const float* lp_lo = g_lepe + obase;
        const float* lp_hi = lp_lo + (size_t)8 * 256;
#pragma unroll
        for (int j2 = 0; j2 < 4; j2++) {
            float2 e0 = *(const float2*)(lp_lo + j2 * 8 + 2 * tg);
            float2 e1 = *(const float2*)(lp_hi + j2 * 8 + 2 * tg);
            *(float2*)(ob_lo + j2 * 8 + 2 * tg) =
                make_float2(O[j2][0] * il + e0.x, O[j2][1] * il + e0.y);
            *(float2*)(ob_hi + j2 * 8 + 2 * tg) =
                make_float2(O[j2][2] * ih + e1.x, O[j2][3] * ih + e1.y);
        }
    }
}

// ---------------------------------------------------------------------------
extern "C" void kernel_launch(void* const* d_in, const int* in_sizes, int n_in,
                              void* d_out, int out_size)
{
    const float* x    = (const float*)d_in[0];
    const float* sinp = (const float*)d_in[1];
    const float* cosp = (const float*)d_in[2];
    const float* mask = (const float*)d_in[3];
    const float* wq   = (const float*)d_in[4];
    const float* bq   = (const float*)d_in[5];
    const float* wk   = (const float*)d_in[6];
    const float* bk   = (const float*)d_in[7];
    const float* wv   = (const float*)d_in[8];
    const float* bv   = (const float*)d_in[9];
    const float* wdw  = (const float*)d_in[10];
    const float* bdw  = (const float*)d_in[11];
    const float* wo   = (const float*)d_in[12];
    const float* bo   = (const float*)d_in[13];
    float* out = (float*)d_out;

    cudaFuncSetAttribute(qkv_gemm,
                         cudaFuncAttributeMaxDynamicSharedMemorySize, QKV_SMEM);
    cudaFuncSetAttribute(out_gemm,
                         cudaFuncAttributeMaxDynamicSharedMemorySize, OGEMM_SMEM);
    cudaFuncSetAttribute(attn_kernel,
                         cudaFuncAttributeMaxDynamicSharedMemorySize,
                         (int)ATTN_SMEM);

    // 1) QKV projection + bias + k-scale + RoPE + permuted layout (fused)
    qkv_gemm<<<dim3(12, 72), 256, QKV_SMEM>>>(x, wq, wk, wv, bq, bk, bv,
                                              sinp, cosp);
    // 2) lepe = dwconv5x5(v)
    dwconv_kernel<<<dim3(36, NH_, B_), 256>>>(wdw, bdw);
    // 3) attention (+lepe add) — 144 blocks = one wave, 32 q-rows/warp
    attn_kernel<<<dim3(B_, 9, NH_), 256, ATTN_SMEM>>>(mask);
    // 4) out = g_attn @ wo + bo — 288 blocks, 2 CTAs/SM, store-side split
    out_gemm<<<dim3(4, 72), 256, OGEMM_SMEM>>>(wo, bo, out);
}

// round 15
// speedup vs baseline: 1.0728x; 1.0728x over previous
#include <cuda_runtime.h>
#include <math.h>
#include <stdint.h>

// Problem shapes
#define B_   2
#define H_   48
#define W_   48
#define C_   256
#define NH_  8
#define HD_  32
#define L_   2304          // H_*W_
#define ML_  4608          // B_*L_

#define KSCALE 0.17677669529663687f   // 32^-0.5

// ---------------------------------------------------------------------------
// Scratch (static __device__ — no allocations allowed)
// d-permuted layouts (chosen for LDS.128 fragment loads in attention):
//   g_q, g_k : pos(d) = (d%4)*8 + d/4   (K-style: thread needs d ≡ tg mod 4)
//   g_v      : pos(d) = (d%8)*4 + d/8   (V-style: thread needs d ≡ gp mod 8)
// ---------------------------------------------------------------------------
__device__ float g_q[B_ * NH_ * L_ * HD_];
__device__ float g_k[B_ * NH_ * L_ * HD_];
__device__ float g_v[B_ * NH_ * L_ * HD_];
__device__ float g_lepe[ML_ * C_];          // [row, C] logical d
__device__ float g_attn[ML_ * C_];          // [row, C] logical d (attn + lepe)

// ---------------------------------------------------------------------------
// Helpers
// ---------------------------------------------------------------------------
__device__ __forceinline__ float tf32r(float x) {
    unsigned u;
    asm("cvt.rna.tf32.f32 %0, %1;" : "=r"(u) : "f"(x));
    return __uint_as_float(u);
}
#define U_(x) __float_as_uint(x)

__device__ __forceinline__ void mma_tf32(float* d, const unsigned* a,
                                         unsigned b0, unsigned b1) {
    asm volatile(
        "mma.sync.aligned.m16n8k8.row.col.f32.tf32.tf32.f32 "
        "{%0,%1,%2,%3}, {%4,%5,%6,%7}, {%8,%9}, {%0,%1,%2,%3};\n"
        : "+f"(d[0]), "+f"(d[1]), "+f"(d[2]), "+f"(d[3])
        : "r"(a[0]), "r"(a[1]), "r"(a[2]), "r"(a[3]), "r"(b0), "r"(b1));
}

__device__ __forceinline__ void cp16(uint32_t dst, const float* src) {
    asm volatile("cp.async.cg.shared.global [%0], [%1], 16;\n"
                 :: "r"(dst), "l"(src));
}
__device__ __forceinline__ void cp_commit() {
    asm volatile("cp.async.commit_group;\n");
}
__device__ __forceinline__ void cp_wait_all() {
    asm volatile("cp.async.wait_group 0;\n" ::: "memory");
}

__device__ __forceinline__ int posK(int d) { return (d & 3) * 8 + (d >> 2); }
__device__ __forceinline__ int posV(int d) { return (d & 7) * 4 + (d >> 3); }

// ===========================================================================
// QKV projection, 3xTF32 split GEMM, cp.async double-buffered k-loop, fused
// bias + k-scale + RoPE + permuted layout scatter. (R13 form, measured)
// Tile 64M x 64N, 256 thr. Grid (12, 72) = 864 blocks -> 2 CTAs/SM.
// ===========================================================================
#define QKV_SMEM (2 * (64 * 36 + 32 * 72) * 4)     // 36864 B

__global__ __launch_bounds__(256, 2) void qkv_gemm(
    const float* __restrict__ x,
    const float* __restrict__ wq, const float* __restrict__ wk,
    const float* __restrict__ wv,
    const float* __restrict__ bq, const float* __restrict__ bk,
    const float* __restrict__ bv,
    const float* __restrict__ sinp, const float* __restrict__ cosp)
{
    extern __shared__ float smg[];
    float* As[2] = { smg,        smg + 4608 };         // [64][36]
    float* Bs[2] = { smg + 2304, smg + 4608 + 2304 };  // [32][72]

    int tid = threadIdx.x;
    int wid = tid >> 5, lane = tid & 31;
    int gp = lane >> 2, tg = lane & 3;
    int wm = wid & 1, wn = wid >> 1;
    int m0 = blockIdx.y * 64;
    int n0 = blockIdx.x * 64;
    int sel = n0 >> 8;               // 0=q 1=k 2=v
    const float* Wm = (sel == 0) ? wq : ((sel == 1) ? wk : wv);
    int nl = n0 & 255;

    int ea_row[2], ea_c4[2], eb_row[2], eb_c4[2];
    uint32_t adst[2][2], bdst[2][2];
#pragma unroll
    for (int i = 0; i < 2; i++) {
        int e = tid + i * 256;
        ea_row[i] = e >> 3;  ea_c4[i] = (e & 7) * 4;
        eb_row[i] = e >> 4;  eb_c4[i] = (e & 15) * 4;
#pragma unroll
        for (int s = 0; s < 2; s++) {
            adst[s][i] = (uint32_t)__cvta_generic_to_shared(
                As[s] + ea_row[i] * 36 + ea_c4[i]);
            bdst[s][i] = (uint32_t)__cvta_generic_to_shared(
                Bs[s] + eb_row[i] * 72 + eb_c4[i]);
        }
    }

#pragma unroll
    for (int i = 0; i < 2; i++) {
        cp16(adst[0][i], x + (size_t)(m0 + ea_row[i]) * 256 + ea_c4[i]);
        cp16(bdst[0][i], Wm + (size_t)eb_row[i] * 256 + nl + eb_c4[i]);
    }
    cp_commit();

    float c[2][2][4];
#pragma unroll
    for (int mf = 0; mf < 2; mf++)
#pragma unroll
        for (int nf = 0; nf < 2; nf++)
#pragma unroll
            for (int q = 0; q < 4; q++) c[mf][nf][q] = 0.f;

    for (int it = 0; it < 8; it++) {
        int cur = it & 1;
        cp_wait_all();
        __syncthreads();
        if (it < 7) {
            int k1 = (it + 1) * 32;
#pragma unroll
            for (int i = 0; i < 2; i++) {
                cp16(adst[cur ^ 1][i],
                     x + (size_t)(m0 + ea_row[i]) * 256 + k1 + ea_c4[i]);
                cp16(bdst[cur ^ 1][i],
                     Wm + (size_t)(k1 + eb_row[i]) * 256 + nl + eb_c4[i]);
            }
            cp_commit();
        }
        const float* Ac = As[cur];
        const float* Bc = Bs[cur];
#pragma unroll
        for (int kc = 0; kc < 4; kc++) {
            int kk = kc * 8 + tg;
            unsigned ah[2][4], al[2][4], bh[2][2], bl[2][2];
#pragma unroll
            for (int mf = 0; mf < 2; mf++) {
                int r = wm * 32 + mf * 16 + gp;
                float a0 = Ac[r * 36 + kk],       a1 = Ac[(r + 8) * 36 + kk];
                float a2 = Ac[r * 36 + kk + 4],   a3 = Ac[(r + 8) * 36 + kk + 4];
                float h0 = tf32r(a0), h1 = tf32r(a1), h2 = tf32r(a2), h3 = tf32r(a3);
                ah[mf][0] = U_(h0); ah[mf][1] = U_(h1);
                ah[mf][2] = U_(h2); ah[mf][3] = U_(h3);
                al[mf][0] = U_(a0 - h0); al[mf][1] = U_(a1 - h1);
                al[mf][2] = U_(a2 - h2); al[mf][3] = U_(a3 - h3);
            }
#pragma unroll
            for (int nf = 0; nf < 2; nf++) {
                int cc = wn * 16 + nf * 8 + gp;
                float b0 = Bc[kk * 72 + cc], b1 = Bc[(kk + 4) * 72 + cc];
                float h0 = tf32r(b0), h1 = tf32r(b1);
                bh[nf][0] = U_(h0); bh[nf][1] = U_(h1);
                bl[nf][0] = U_(b0 - h0); bl[nf][1] = U_(b1 - h1);
            }
#pragma unroll
            for (int mf = 0; mf < 2; mf++)
#pragma unroll
                for (int nf = 0; nf < 2; nf++) {
                    mma_tf32(c[mf][nf], ah[mf], bh[nf][0], bh[nf][1]);
                    mma_tf32(c[mf][nf], al[mf], bh[nf][0], bh[nf][1]);
                    mma_tf32(c[mf][nf], ah[mf], bl[nf][0], bl[nf][1]);
                }
        }
        __syncthreads();
    }

    // ---- epilogue: bias (+scale) (+rope) + permuted scatter ----
#pragma unroll
    for (int mf = 0; mf < 2; mf++) {
#pragma unroll
        for (int nf = 0; nf < 2; nf++) {
            int colg = n0 + wn * 16 + nf * 8 + 2 * tg;
            int cl = colg & 255;
            int d = cl & 31, head = cl >> 5;
#pragma unroll
            for (int half = 0; half < 2; half++) {
                int row = m0 + wm * 32 + mf * 16 + gp + half * 8;
                float v0 = c[mf][nf][half * 2 + 0];
                float v1 = c[mf][nf][half * 2 + 1];
                int bb = row / L_, l = row - bb * L_;
                size_t base = ((size_t)(bb * NH_ + head) * L_ + l) * HD_;
                if (sel == 0) {
                    v0 += bq[cl]; v1 += bq[cl + 1];
                    float s0 = sinp[l * HD_ + d], s1 = sinp[l * HD_ + d + 1];
                    float c0 = cosp[l * HD_ + d], c1 = cosp[l * HD_ + d + 1];
                    g_q[base + posK(d)]     = v0 * c0 - v1 * s0;
                    g_q[base + posK(d + 1)] = v1 * c1 + v0 * s1;
                } else if (sel == 1) {
                    v0 = (v0 + bk[cl]) * KSCALE;
                    v1 = (v1 + bk[cl + 1]) * KSCALE;
                    float s0 = sinp[l * HD_ + d], s1 = sinp[l * HD_ + d + 1];
                    float c0 = cosp[l * HD_ + d], c1 = cosp[l * HD_ + d + 1];
                    g_k[base + posK(d)]     = v0 * c0 - v1 * s0;
                    g_k[base + posK(d + 1)] = v1 * c1 + v0 * s1;
                } else {
                    g_v[base + posV(d)]     = v0 + bv[cl];
                    g_v[base + posV(d + 1)] = v1 + bv[cl + 1];
                }
            }
        }
    }
}

// ===========================================================================
// Output projection, 3xTF32 split GEMM, store-side split (R14 measured 17.4us)
// out[4608 x 256] = g_attn @ wo + bo.
// Tile 64M x 64N, grid (4, 72) = 288 blocks -> 2 CTAs/SM.
// ===========================================================================
#define OGEMM_SMEM ((2 * 64 * 36 + 2 * 32 * 72) * 4)     // 36864 B

__global__ __launch_bounds__(256, 2) void out_gemm(
    const float* __restrict__ wo, const float* __restrict__ bo,
    float* __restrict__ out)
{
    extern __shared__ float smg[];
    float* Ah = smg;                 // [64][36]
    float* Al = Ah + 64 * 36;
    float* Bh = Al + 64 * 36;        // [32][72]
    float* Bl = Bh + 32 * 72;

    int tid = threadIdx.x;
    int wid = tid >> 5, lane = tid & 31;
    int gp = lane >> 2, tg = lane & 3;
    int wm = wid & 1, wn = wid >> 1;
    int m0 = blockIdx.y * 64;
    int n0 = blockIdx.x * 64;

    float c[2][2][4];
#pragma unroll
    for (int mf = 0; mf < 2; mf++)
#pragma unroll
        for (int nf = 0; nf < 2; nf++)
#pragma unroll
            for (int q = 0; q < 4; q++) c[mf][nf][q] = 0.f;

    for (int k0 = 0; k0 < 256; k0 += 32) {
#pragma unroll
        for (int i = 0; i < 2; i++) {
            int e = tid + i * 256;
            int row = e >> 3, c4 = (e & 7) * 4;
            size_t off = (size_t)(m0 + row) * 256 + k0 + c4;
            float4 a4 = *(const float4*)(g_attn + off);
            float h0 = tf32r(a4.x), h1 = tf32r(a4.y),
                  h2 = tf32r(a4.z), h3 = tf32r(a4.w);
            float* ah = Ah + row * 36 + c4;
            float* al = Al + row * 36 + c4;
            ah[0] = h0; ah[1] = h1; ah[2] = h2; ah[3] = h3;
            al[0] = a4.x - h0; al[1] = a4.y - h1;
            al[2] = a4.z - h2; al[3] = a4.w - h3;
        }
#pragma unroll
        for (int i = 0; i < 2; i++) {
            int e = tid + i * 256;
            int row = e >> 4, c4 = (e & 15) * 4;
            float4 b4 = *(const float4*)(wo + (size_t)(k0 + row) * 256 + n0 + c4);
            float h0 = tf32r(b4.x), h1 = tf32r(b4.y),
                  h2 = tf32r(b4.z), h3 = tf32r(b4.w);
            float* bh = Bh + row * 72 + c4;
            float* bl = Bl + row * 72 + c4;
            bh[0] = h0; bh[1] = h1; bh[2] = h2; bh[3] = h3;
            bl[0] = b4.x - h0; bl[1] = b4.y - h1;
            bl[2] = b4.z - h2; bl[3] = b4.w - h3;
        }
        __syncthreads();
#pragma unroll
        for (int kc = 0; kc < 4; kc++) {
            int kk = kc * 8 + tg;
            unsigned ah[2][4], al[2][4], bh[2][2], bl[2][2];
#pragma unroll
            for (int mf = 0; mf < 2; mf++) {
                int r = wm * 32 + mf * 16 + gp;
                ah[mf][0] = U_(Ah[r * 36 + kk]);
                ah[mf][1] = U_(Ah[(r + 8) * 36 + kk]);
                ah[mf][2] = U_(Ah[r * 36 + kk + 4]);
                ah[mf][3] = U_(Ah[(r + 8) * 36 + kk + 4]);
                al[mf][0] = U_(Al[r * 36 + kk]);
                al[mf][1] = U_(Al[(r + 8) * 36 + kk]);
                al[mf][2] = U_(Al[r * 36 + kk + 4]);
                al[mf][3] = U_(Al[(r + 8) * 36 + kk + 4]);
            }
#pragma unroll
            for (int nf = 0; nf < 2; nf++) {
                int cc = wn * 16 + nf * 8 + gp;
                bh[nf][0] = U_(Bh[kk * 72 + cc]);
                bh[nf][1] = U_(Bh[(kk + 4) * 72 + cc]);
                bl[nf][0] = U_(Bl[kk * 72 + cc]);
                bl[nf][1] = U_(Bl[(kk + 4) * 72 + cc]);
            }
#pragma unroll
            for (int mf = 0; mf < 2; mf++)
#pragma unroll
                for (int nf = 0; nf < 2; nf++) {
                    mma_tf32(c[mf][nf], ah[mf], bh[nf][0], bh[nf][1]);
                    mma_tf32(c[mf][nf], al[mf], bh[nf][0], bh[nf][1]);
                    mma_tf32(c[mf][nf], ah[mf], bl[nf][0], bl[nf][1]);
                }
        }
        __syncthreads();
    }

#pragma unroll
    for (int mf = 0; mf < 2; mf++)
#pragma unroll
        for (int nf = 0; nf < 2; nf++) {
            int colg = n0 + wn * 16 + nf * 8 + 2 * tg;
            float b0 = bo[colg], b1 = bo[colg + 1];
#pragma unroll
            for (int half = 0; half < 2; half++) {
                int row = m0 + wm * 32 + mf * 16 + gp + half * 8;
                *(float2*)(out + (size_t)row * 256 + colg) =
                    make_float2(c[mf][nf][half * 2 + 0] + b0,
                                c[mf][nf][half * 2 + 1] + b1);
            }
        }
}

// ---------------------------------------------------------------------------
// Depthwise 5x5 conv (lepe) on v (V-permuted layout), padding 2 -> [row, C]
// ---------------------------------------------------------------------------
__global__ __launch_bounds__(256) void dwconv_kernel(
    const float* __restrict__ wdw, const float* __restrict__ bdw)
{
    __shared__ float tile[144][32];   // 12x12 halo x 32 stored-positions
    int b = blockIdx.z, n = blockIdx.y;
    int t = blockIdx.x;
    int ty0 = (t / 6) * 8, tx0 = (t % 6) * 8;
    const float* vb = g_v + (size_t)(b * NH_ + n) * L_ * HD_;

    for (int e = threadIdx.x; e < 144 * 32; e += 256) {
        int ch = e & 31, sp = e >> 5;
        int hy = ty0 + sp / 12 - 2, wx = tx0 + sp % 12 - 2;
        float val = 0.f;
        if (hy >= 0 && hy < H_ && wx >= 0 && wx < W_)
            val = vb[(size_t)(hy * W_ + wx) * HD_ + ch];
        tile[sp][ch] = val;
    }
    __syncthreads();

    for (int o = threadIdx.x; o < 64 * 32; o += 256) {
        int ch = o & 31, sp = o >> 5;           // ch = stored position
        int dlog = (ch & 3) * 8 + (ch >> 2);    // invert posV
        int y = sp >> 3, x = sp & 7;
        float acc = bdw[n * 32 + dlog];
#pragma unroll
        for (int ky = 0; ky < 5; ky++)
#pragma unroll
            for (int kx = 0; kx < 5; kx++)
                acc = fmaf(tile[(y + ky) * 12 + x + kx][ch],
                           wdw[(ky * 5 + kx) * 256 + n * 32 + dlog], acc);
        g_lepe[((size_t)(b * L_) + (ty0 + y) * W_ + tx0 + x) * 256 + n * 32 + dlog] = acc;
    }
}

// ---------------------------------------------------------------------------
// Flash attention v7 (R13 measured form) — 2 CTAs/SM, 16 q-rows/warp.
//  * 256 threads (8 warps), 128 q-rows/CTA, grid (B,18,NH) = 288 = 2 CTAs/SM
//  * 64-key tiles, cp.async double-buffered K/V, mask folded into accum init
//  * no max-shift softmax (bounded scores), per-thread deferred denominators
//  * shfl-free P path via permuted V rows (register relabel {s0,s2,s1,s3})
//  * lepe fused into the epilogue (g_attn = attn + lepe)
// Smem: Q[128][36] + 2xK[64][36] + 2xV[64][40] = 57344 B.
// ---------------------------------------------------------------------------
#define ATTN_SMEM (size_t)(57344)

__global__ __launch_bounds__(256, 2) void attn_kernel(const float* __restrict__ mask)
{
    extern __shared__ float sm[];
    float* Qs = sm;                                  // 128 x 36 = 4608 f
    float* Kb[2] = { sm + 4608, sm + 6912 };         // 64 x 36 each
    float* Vb[2] = { sm + 9216, sm + 11776 };        // 64 x 40 each

    int b = blockIdx.x, qt = blockIdx.y, n = blockIdx.z;
    int bn = b * NH_ + n;
    const float* qb = g_q + (size_t)bn * L_ * HD_;
    const float* kb = g_k + (size_t)bn * L_ * HD_;
    const float* vb = g_v + (size_t)bn * L_ * HD_;
    int q0 = qt * 128;

    int tid = threadIdx.x;
    int wr = tid >> 5;        // 0..7, warp owns rows [wr*16, wr*16+16)
    int lane = tid & 31;
    int gp = lane >> 2;
    int tg = lane & 3;
    int r_lo = wr * 16 + gp;

    // cp.async mapping: 64 rows x 8 chunks(16B) = 512 -> 2 chunks per thread
    uint32_t kdst[2][2], vdst[2][2];
    const float *ksrc[2], *vsrc[2];
#pragma unroll
    for (int i = 0; i < 2; i++) {
        int e = tid + i * 256;
        int erow = e >> 3;
        int ecol = (e & 7) * 4;
        // V row permutation: key loc -> slot (loc>>1)+(loc&1)*4 within 8-group
        int vrow = (erow & ~7) + ((erow & 7) >> 1) + ((erow & 1) << 2);
        kdst[0][i] = (uint32_t)__cvta_generic_to_shared(Kb[0] + erow * 36 + ecol);
        kdst[1][i] = (uint32_t)__cvta_generic_to_shared(Kb[1] + erow * 36 + ecol);
        vdst[0][i] = (uint32_t)__cvta_generic_to_shared(Vb[0] + vrow * 40 + ecol);
        vdst[1][i] = (uint32_t)__cvta_generic_to_shared(Vb[1] + vrow * 40 + ecol);
        ksrc[i] = kb + (size_t)erow * HD_ + ecol;
        vsrc[i] = vb + (size_t)erow * HD_ + ecol;
    }

    const float* mrow_lo_base =
        mask + (size_t)n * L_ * L_ + (size_t)(q0 + r_lo) * L_;
    const float* mrow_hi_base = mrow_lo_base + (size_t)8 * L_;

    // ---- prologue ----
#pragma unroll
    for (int i = 0; i < 2; i++) {
        cp16(kdst[0][i], ksrc[i]);
        cp16(vdst[0][i], vsrc[i]);
    }
    cp_commit();

    for (int e = tid; e < 128 * 8; e += 256) {
        int row = e >> 3, cq = (e & 7) * 4;
        *(float4*)(Qs + row * 36 + cq) =
            *(const float4*)(qb + (size_t)(q0 + row) * HD_ + cq);
    }
    __syncthreads();

    // ---- Q A-fragments from permuted rows (2x LDS.128 per row) ----
    unsigned qa[4][4];
    {
        float4 qL0 = *(const float4*)(Qs + r_lo * 36 + tg * 8);
        float4 qL1 = *(const float4*)(Qs + r_lo * 36 + tg * 8 + 4);
        float4 qH0 = *(const float4*)(Qs + (r_lo + 8) * 36 + tg * 8);
        float4 qH1 = *(const float4*)(Qs + (r_lo + 8) * 36 + tg * 8 + 4);
        qa[0][0] = U_(qL0.x); qa[0][1] = U_(qH0.x); qa[0][2] = U_(qL0.y); qa[0][3] = U_(qH0.y);
        qa[1][0] = U_(qL0.z); qa[1][1] = U_(qH0.z); qa[1][2] = U_(qL0.w); qa[1][3] = U_(qH0.w);
        qa[2][0] = U_(qL1.x); qa[2][1] = U_(qH1.x); qa[2][2] = U_(qL1.y); qa[2][3] = U_(qH1.y);
        qa[3][0] = U_(qL1.z); qa[3][1] = U_(qH1.z); qa[3][2] = U_(qL1.w); qa[3][3] = U_(qH1.w);
    }

    float ps_lo = 0.f, ps_hi = 0.f;      // per-thread partial softmax denoms
    float O[4][4];
#pragma unroll
    for (int j = 0; j < 4; j++) { O[j][0] = O[j][1] = O[j][2] = O[j][3] = 0.f; }

    for (int kt = 0; kt < 36; kt++) {
        int k0 = kt * 64;
        int cur = kt & 1;

        // ---- mask loads first (latency overlaps cp.async wait) ----
        float s[8][4];
        {
            const float* mrow_lo = mrow_lo_base + k0;
            const float* mrow_hi = mrow_hi_base + k0;
#pragma unroll
            for (int j = 0; j < 8; j++) {
                int col = j * 8 + 2 * tg;
                float2 mlo = *(const float2*)(mrow_lo + col);
                float2 mhi = *(const float2*)(mrow_hi + col);
                s[j][0] = mlo.x; s[j][1] = mlo.y;
                s[j][2] = mhi.x; s[j][3] = mhi.y;
            }
        }

        cp_wait_all();
        __syncthreads();

        if (kt + 1 < 36) {
#pragma unroll
            for (int i = 0; i < 2; i++) {
                cp16(kdst[cur ^ 1][i], ksrc[i] + (size_t)(k0 + 64) * HD_);
                cp16(vdst[cur ^ 1][i], vsrc[i] + (size_t)(k0 + 64) * HD_);
            }
            cp_commit();
        }

        const float* Ks = Kb[cur];
        const float* Vs = Vb[cur];

        // ---- S = mask + Q @ K^T (wide K fragment loads) ----
#pragma unroll
        for (int j = 0; j < 8; j++) {
            const float* kr = Ks + (8 * j + gp) * 36 + tg * 8;
            float4 kf0 = *(const float4*)(kr);
            float4 kf1 = *(const float4*)(kr + 4);
            mma_tf32(s[j], qa[0], U_(kf0.x), U_(kf0.y));
            mma_tf32(s[j], qa[1], U_(kf0.z), U_(kf0.w));
            mma_tf32(s[j], qa[2], U_(kf1.x), U_(kf1.y));
            mma_tf32(s[j], qa[3], U_(kf1.z), U_(kf1.w));
        }

        // ---- P = exp(S) (no max-shift; scores bounded), accumulate denom ----
#pragma unroll
        for (int j = 0; j < 8; j++) {
            s[j][0] = __expf(s[j][0]);
            s[j][1] = __expf(s[j][1]);
            s[j][2] = __expf(s[j][2]);
            s[j][3] = __expf(s[j][3]);
            ps_lo += s[j][0] + s[j][1];
            ps_hi += s[j][2] + s[j][3];
        }

        // ---- O += P @ V (register-relabel A-fragment, permuted V rows) ----
#pragma unroll
        for (int kc2 = 0; kc2 < 8; kc2++) {
            unsigned pa[4];
            pa[0] = U_(s[kc2][0]);   // P[gp,   2tg  ] -> k-slot tg
            pa[1] = U_(s[kc2][2]);   // P[gp+8, 2tg  ]
            pa[2] = U_(s[kc2][1]);   // P[gp,   2tg+1] -> k-slot tg+4
            pa[3] = U_(s[kc2][3]);   // P[gp+8, 2tg+1]
            float4 vA = *(const float4*)(Vs + (kc2 * 8 + tg) * 40 + gp * 4);
            float4 vB = *(const float4*)(Vs + (kc2 * 8 + tg + 4) * 40 + gp * 4);
            mma_tf32(O[0], pa, U_(vA.x), U_(vB.x));
            mma_tf32(O[1], pa, U_(vA.y), U_(vB.y));
            mma_tf32(O[2], pa, U_(vA.z), U_(vB.z));
            mma_tf32(O[3], pa, U_(vA.w), U_(vB.w));
        }
    }

    // ---- epilogue: reduce denoms, O / l + lepe, write logical d ----
    ps_lo += __shfl_xor_sync(0xffffffffu, ps_lo, 1);
    ps_lo += __shfl_xor_sync(0xffffffffu, ps_lo, 2);
    ps_hi += __shfl_xor_sync(0xffffffffu, ps_hi, 1);
    ps_hi += __shfl_xor_sync(0xffffffffu, ps_hi, 2);
    float inv_lo = 1.f / ps_lo, inv_hi = 1.f / ps_hi;

    size_t obase = (size_t)(b * L_ + q0 + r_lo) * 256 + n * 32;
    float* ob_lo = g_attn + obase;
    float* ob_hi = ob_lo + (size_t)8 * 256;
    const float* lp_lo = g_lepe + obase;
    const float* lp_hi = lp_lo + (size_t)8 * 256;
#pragma unroll
    for (int j2 = 0; j2 < 4; j2++) {
        float2 e0 = *(const float2*)(lp_lo + j2 * 8 + 2 * tg);
        float2 e1 = *(const float2*)(lp_hi + j2 * 8 + 2 * tg);
        *(float2*)(ob_lo + j2 * 8 + 2 * tg) =
            make_float2(O[j2][0] * inv_lo + e0.x, O[j2][1] * inv_lo + e0.y);
        *(float2*)(ob_hi + j2 * 8 + 2 * tg) =
            make_float2(O[j2][2] * inv_hi + e1.x, O[j2][3] * inv_hi + e1.y);
    }
}

// ---------------------------------------------------------------------------
extern "C" void kernel_launch(void* const* d_in, const int* in_sizes, int n_in,
                              void* d_out, int out_size)
{
    const float* x    = (const float*)d_in[0];
    const float* sinp = (const float*)d_in[1];
    const float* cosp = (const float*)d_in[2];
    const float* mask = (const float*)d_in[3];
    const float* wq   = (const float*)d_in[4];
    const float* bq   = (const float*)d_in[5];
    const float* wk   = (const float*)d_in[6];
    const float* bk   = (const float*)d_in[7];
    const float* wv   = (const float*)d_in[8];
    const float* bv   = (const float*)d_in[9];
    const float* wdw  = (const float*)d_in[10];
    const float* bdw  = (const float*)d_in[11];
    const float* wo   = (const float*)d_in[12];
    const float* bo   = (const float*)d_in[13];
    float* out = (float*)d_out;

    cudaFuncSetAttribute(qkv_gemm,
                         cudaFuncAttributeMaxDynamicSharedMemorySize, QKV_SMEM);
    cudaFuncSetAttribute(out_gemm,
                         cudaFuncAttributeMaxDynamicSharedMemorySize, OGEMM_SMEM);
    cudaFuncSetAttribute(attn_kernel,
                         cudaFuncAttributeMaxDynamicSharedMemorySize,
                         (int)ATTN_SMEM);

    // 1) QKV projection + bias + k-scale + RoPE + permuted layout (fused)
    qkv_gemm<<<dim3(12, 72), 256, QKV_SMEM>>>(x, wq, wk, wv, bq, bk, bv,
                                              sinp, cosp);
    // 2) lepe = dwconv5x5(v)
    dwconv_kernel<<<dim3(36, NH_, B_), 256>>>(wdw, bdw);
    // 3) attention (+lepe add) — 288 blocks = 2 CTAs/SM
    attn_kernel<<<dim3(B_, 18, NH_), 256, ATTN_SMEM>>>(mask);
    // 4) out = g_attn @ wo + bo — 288 blocks, 2 CTAs/SM, store-side split
    out_gemm<<<dim3(4, 72), 256, OGEMM_SMEM>>>(wo, bo, out);
}